// round 2
// baseline (speedup 1.0000x reference)
#include <cuda_runtime.h>
#include <math.h>
#include <stdint.h>

#define B_    512
#define T_    76
#define HIST  10
#define H_    256
#define L_    8
#define NSTEP 64
#define MLPH  15000
#define K1    130
#define NBLK  128

// ---------------- static device scratch ----------------
__device__ __align__(16) float g_mlp[B_ * MLPH];
__device__ __align__(16) float g_h[2][L_][B_][H_];
__device__ __align__(16) float g_c[L_][B_][H_];
__device__ unsigned g_bar_cnt = 0;
__device__ volatile unsigned g_bar_gen = 0;

// ---------------- helpers ----------------
__device__ __forceinline__ float tf32f(float x) {
    uint32_t r; asm("cvt.rna.tf32.f32 %0, %1;" : "=r"(r) : "f"(x));
    return __uint_as_float(r);
}
__device__ __forceinline__ void mma8(float c[4], uint32_t a0, uint32_t a1, uint32_t a2, uint32_t a3,
                                     uint32_t b0, uint32_t b1) {
    asm volatile(
        "mma.sync.aligned.m16n8k8.row.col.f32.tf32.tf32.f32 "
        "{%0,%1,%2,%3},{%4,%5,%6,%7},{%8,%9},{%0,%1,%2,%3};\n"
        : "+f"(c[0]), "+f"(c[1]), "+f"(c[2]), "+f"(c[3])
        : "r"(a0), "r"(a1), "r"(a2), "r"(a3), "r"(b0), "r"(b1));
}
__device__ __forceinline__ float sigf(float x) { return __fdividef(1.f, 1.f + __expf(-x)); }
__device__ __forceinline__ float tanhfast(float x) { return 2.f * sigf(2.f * x) - 1.f; }

__device__ __forceinline__ void grid_sync(unsigned nb) {
    __syncthreads();
    if (threadIdx.x == 0) {
        unsigned gen = g_bar_gen;
        __threadfence();
        if (atomicAdd(&g_bar_cnt, 1u) == nb - 1u) {
            g_bar_cnt = 0u;
            __threadfence();
            g_bar_gen = gen + 1u;
        } else {
            while (g_bar_gen == gen) { __nanosleep(64); }
            __threadfence();
        }
    }
    __syncthreads();
}

// ---------------- GEMM1: mlp = relu(enc @ W1^T + b1), fp32 ----------------
__global__ void __launch_bounds__(256) k_gemm1(const float* __restrict__ states,
                                               const float* __restrict__ acts,
                                               const float* __restrict__ W1,
                                               const float* __restrict__ b1) {
    const int bm = blockIdx.x & 15;
    const int bn = blockIdx.x >> 4;
    const int n0 = bn * 128;
    const int tid = threadIdx.x;
    __shared__ float enc_s[32][132];
    __shared__ float w_s[128][33];

    for (int i = tid; i < 32 * K1; i += 256) {
        const int r = i / K1, k = i % K1;
        const int b = bm * 32 + r;
        const int tt = k / 13, j = k % 13;
        enc_s[r][k] = (j < 9) ? states[(b * T_ + tt) * 12 + 3 + j]
                              : acts[(b * T_ + tt) * 4 + (j - 9)];
    }

    float acc[4][4];
#pragma unroll
    for (int ii = 0; ii < 4; ii++)
#pragma unroll
        for (int jj = 0; jj < 4; jj++) acc[ii][jj] = 0.f;

    const int tr = tid >> 5;
    const int tc = tid & 31;

    for (int k0 = 0; k0 < K1; k0 += 32) {
        const int kn = min(32, K1 - k0);
        __syncthreads();
        for (int i = tid; i < 128 * 32; i += 256) {
            const int c = i >> 5, kk = i & 31;
            const int n = n0 + c;
            w_s[c][kk] = (kk < kn && n < MLPH) ? W1[n * K1 + k0 + kk] : 0.f;
        }
        __syncthreads();
        for (int kk = 0; kk < kn; kk++) {
            float a[4], w[4];
#pragma unroll
            for (int ii = 0; ii < 4; ii++) a[ii] = enc_s[tr + 8 * ii][k0 + kk];
#pragma unroll
            for (int jj = 0; jj < 4; jj++) w[jj] = w_s[tc + 32 * jj][kk];
#pragma unroll
            for (int ii = 0; ii < 4; ii++)
#pragma unroll
                for (int jj = 0; jj < 4; jj++) acc[ii][jj] += a[ii] * w[jj];
        }
    }
#pragma unroll
    for (int ii = 0; ii < 4; ii++)
#pragma unroll
        for (int jj = 0; jj < 4; jj++) {
            const int b = bm * 32 + tr + 8 * ii;
            const int n = n0 + tc + 32 * jj;
            if (n < MLPH) g_mlp[(size_t)b * MLPH + n] = fmaxf(acc[ii][jj] + b1[n], 0.f);
        }
}

// ---------------- GEMM2: hc = mlp @ W2^T + b2 -> h0 (parity 1) / c0, tf32 ----------------
__global__ void __launch_bounds__(256) k_gemm2(const float* __restrict__ W2,
                                               const float* __restrict__ b2) {
    const int bm = blockIdx.x & 7;
    const int bn = blockIdx.x >> 3;
    const int tid = threadIdx.x;
    const int warp = tid >> 5, lane = tid & 31;
    const int wm = warp >> 1, wn = warp & 1;
    const int g = lane >> 2, tq = lane & 3;

    __shared__ float As[64][36];
    __shared__ float Bs[64][36];

    float acc[4][4];
#pragma unroll
    for (int j = 0; j < 4; j++)
#pragma unroll
        for (int d = 0; d < 4; d++) acc[j][d] = 0.f;

    for (int k0 = 0; k0 < MLPH; k0 += 32) {
        // stage to regs (overlaps prior mma)
        float4 av[2], bv[2];
#pragma unroll
        for (int q = 0; q < 2; q++) {
            const int i = tid + 256 * q;
            const int r = i >> 3, kq = (i & 7) << 2;
            const int k = k0 + kq;
            const float* ap = &g_mlp[(size_t)(bm * 64 + r) * MLPH];
            const float* bp = &W2[(size_t)(bn * 64 + r) * MLPH];
            if (k + 3 < MLPH) {
                av[q] = *(const float4*)(ap + k);
                bv[q] = *(const float4*)(bp + k);
            } else {
                av[q].x = (k + 0 < MLPH) ? ap[k + 0] : 0.f;
                av[q].y = (k + 1 < MLPH) ? ap[k + 1] : 0.f;
                av[q].z = (k + 2 < MLPH) ? ap[k + 2] : 0.f;
                av[q].w = (k + 3 < MLPH) ? ap[k + 3] : 0.f;
                bv[q].x = (k + 0 < MLPH) ? bp[k + 0] : 0.f;
                bv[q].y = (k + 1 < MLPH) ? bp[k + 1] : 0.f;
                bv[q].z = (k + 2 < MLPH) ? bp[k + 2] : 0.f;
                bv[q].w = (k + 3 < MLPH) ? bp[k + 3] : 0.f;
            }
        }
        __syncthreads();
#pragma unroll
        for (int q = 0; q < 2; q++) {
            const int i = tid + 256 * q;
            const int r = i >> 3, kq = (i & 7) << 2;
            As[r][kq + 0] = tf32f(av[q].x); As[r][kq + 1] = tf32f(av[q].y);
            As[r][kq + 2] = tf32f(av[q].z); As[r][kq + 3] = tf32f(av[q].w);
            Bs[r][kq + 0] = tf32f(bv[q].x); Bs[r][kq + 1] = tf32f(bv[q].y);
            Bs[r][kq + 2] = tf32f(bv[q].z); Bs[r][kq + 3] = tf32f(bv[q].w);
        }
        __syncthreads();
#pragma unroll
        for (int k8 = 0; k8 < 4; k8++) {
            const int kc = k8 * 8 + tq;
            const int ar = wm * 16 + g;
            uint32_t a0 = __float_as_uint(As[ar][kc]);
            uint32_t a1 = __float_as_uint(As[ar + 8][kc]);
            uint32_t a2 = __float_as_uint(As[ar][kc + 4]);
            uint32_t a3 = __float_as_uint(As[ar + 8][kc + 4]);
#pragma unroll
            for (int j = 0; j < 4; j++) {
                const int bc = wn * 32 + j * 8 + g;
                mma8(acc[j], a0, a1, a2, a3,
                     __float_as_uint(Bs[bc][kc]), __float_as_uint(Bs[bc][kc + 4]));
            }
        }
    }
#pragma unroll
    for (int j = 0; j < 4; j++)
#pragma unroll
        for (int d = 0; d < 4; d++) {
            const int r = wm * 16 + g + ((d & 2) ? 8 : 0);
            const int c = wn * 32 + j * 8 + tq * 2 + (d & 1);
            const int b = bm * 64 + r;
            const int n = bn * 64 + c;
            const float v = acc[j][d] + b2[n];
            const int l = n >> 9, rem = n & 511;
            if (rem < H_) g_h[1][l][b][rem] = v;
            else          g_c[l][b][rem - H_] = v;
        }
}

// ---------------- rollout: persistent kernel ----------------
__global__ void __launch_bounds__(256) k_rollout(
    const float* __restrict__ states, const float* __restrict__ acts,
    const float* __restrict__ dts,
    const float* __restrict__ Wih0, const float* __restrict__ Whh0,
    const float* __restrict__ bih0, const float* __restrict__ bhh0,
    const float* __restrict__ Wih, const float* __restrict__ Whh,
    const float* __restrict__ bih, const float* __restrict__ bhh,
    const float* __restrict__ Wfc, const float* __restrict__ bfc,
    float* __restrict__ out)
{
    const int bm = blockIdx.x >> 3;   // 0..15 (rows)
    const int bh = blockIdx.x & 7;    // 0..7  (h cols)
    const int tid = threadIdx.x;
    const int warp = tid >> 5, lane = tid & 31;
    const int wm = warp >> 2, wn = warp & 3;
    const int g = lane >> 2, tq = lane & 3;
    const int row0 = bm * 32;
    const int hc0 = bh * 32;

    __shared__ float As[32][36];
    __shared__ float Bs[128][36];
    __shared__ float Gs[32][132];
    __shared__ float xs[32][16];
    __shared__ float bias_s[8][128];

    // biases (step-invariant)
    for (int i = tid; i < 1024; i += 256) {
        const int l = i >> 7;
        const int gate = (i >> 5) & 3;
        const int hc = i & 31;
        const int n = gate * 256 + hc0 + hc;
        float v;
        if (l == 0) v = bih0[n] + bhh0[n];
        else        v = bih[(l - 1) * 1024 + n] + bhh[(l - 1) * 1024 + n];
        bias_s[l][gate * 32 + hc] = v;
    }
    // c0 into registers
    float c_reg[8][4];
#pragma unroll
    for (int l = 0; l < 8; l++)
#pragma unroll
        for (int e = 0; e < 4; e++) {
            const int lin = tid + 256 * e;
            const int r = lin >> 5, hc = lin & 31;
            c_reg[l][e] = g_c[l][row0 + r][hc0 + hc];
        }
    // pred0
    {
        const int r = tid >> 3, j = tid & 7;
        xs[r][1 + j] = states[((row0 + r) * T_ + HIST) * 12 + 3 + j];
        if (tid < 32) xs[tid][9] = states[((row0 + tid) * T_ + HIST) * 12 + 11];
        if (tid < 32) { xs[tid][14] = 0.f; xs[tid][15] = 0.f; }
    }
    __syncthreads();

    for (int t = 0; t < NSTEP; t++) {
        const int cur = t & 1, old = cur ^ 1;
        // dt / act for this step
        if (tid < 32)  xs[tid][0] = dts[(row0 + tid) * T_ + HIST + 1 + t];
        if (tid < 128) {
            const int r = tid >> 2, j = tid & 3;
            xs[r][10 + j] = acts[((row0 + r) * T_ + HIST + t) * 4 + j];
        }
        __syncthreads();

        for (int l = 0; l < 8; l++) {
            float acc[4][4];
#pragma unroll
            for (int j = 0; j < 4; j++)
#pragma unroll
                for (int d = 0; d < 4; d++) acc[j][d] = 0.f;

            // --- layer0: K=16 padded x-tile (xs @ Wih0^T) ---
            if (l == 0) {
                // stage B rows (scalar, 14 valid k)
                float breg[8];
                const int c = tid >> 1, kb = (tid & 1) << 3;
                const int n = ((c >> 5) << 8) + hc0 + (c & 31);
#pragma unroll
                for (int q = 0; q < 8; q++) {
                    const int k = kb + q;
                    breg[q] = (k < 14) ? __ldg(&Wih0[n * 14 + k]) : 0.f;
                }
                const int ra = tid >> 3, ka = (tid & 7) << 1;
                float x0 = (ka < 14) ? xs[ra][ka] : 0.f;
                float x1 = (ka + 1 < 14) ? xs[ra][ka + 1] : 0.f;
                __syncthreads();
                As[ra][ka] = tf32f(x0); As[ra][ka + 1] = tf32f(x1);
#pragma unroll
                for (int q = 0; q < 8; q++) Bs[c][kb + q] = tf32f(breg[q]);
                __syncthreads();
#pragma unroll
                for (int k8 = 0; k8 < 2; k8++) {
                    const int kc = k8 * 8 + tq;
                    const int ar = wm * 16 + g;
                    uint32_t a0 = __float_as_uint(As[ar][kc]);
                    uint32_t a1 = __float_as_uint(As[ar + 8][kc]);
                    uint32_t a2 = __float_as_uint(As[ar][kc + 4]);
                    uint32_t a3 = __float_as_uint(As[ar + 8][kc + 4]);
#pragma unroll
                    for (int j = 0; j < 4; j++) {
                        const int bc = wn * 32 + j * 8 + g;
                        mma8(acc[j], a0, a1, a2, a3,
                             __float_as_uint(Bs[bc][kc]), __float_as_uint(Bs[bc][kc + 4]));
                    }
                }
            }

            // --- up to two K=256 passes ---
            const int npass = (l == 0) ? 1 : 2;
            for (int p = 0; p < npass; p++) {
                const float* src;
                const float* W;
                if (l == 0) { src = &g_h[old][0][row0][0]; W = Whh0; }
                else if (p == 0) { src = &g_h[cur][l - 1][row0][0]; W = Wih + (size_t)(l - 1) * 1024 * 256; }
                else { src = &g_h[old][l][row0][0]; W = Whh + (size_t)(l - 1) * 1024 * 256; }

                for (int k0 = 0; k0 < 256; k0 += 32) {
                    float4 av, bv[4];
                    {
                        const int r = tid >> 3, kq = (tid & 7) << 2;
                        av = __ldcg((const float4*)(src + r * 256 + k0 + kq));
                    }
                    {
                        const int c = tid >> 1, kb = (tid & 1) << 4;
                        const int n = ((c >> 5) << 8) + hc0 + (c & 31);
                        const float* wp = W + (size_t)n * 256 + k0 + kb;
#pragma unroll
                        for (int q = 0; q < 4; q++) bv[q] = __ldg((const float4*)(wp + q * 4));
                    }
                    __syncthreads();
                    {
                        const int r = tid >> 3, kq = (tid & 7) << 2;
                        As[r][kq] = tf32f(av.x); As[r][kq + 1] = tf32f(av.y);
                        As[r][kq + 2] = tf32f(av.z); As[r][kq + 3] = tf32f(av.w);
                        const int c = tid >> 1, kb = (tid & 1) << 4;
#pragma unroll
                        for (int q = 0; q < 4; q++) {
                            Bs[c][kb + q * 4 + 0] = tf32f(bv[q].x);
                            Bs[c][kb + q * 4 + 1] = tf32f(bv[q].y);
                            Bs[c][kb + q * 4 + 2] = tf32f(bv[q].z);
                            Bs[c][kb + q * 4 + 3] = tf32f(bv[q].w);
                        }
                    }
                    __syncthreads();
#pragma unroll
                    for (int k8 = 0; k8 < 4; k8++) {
                        const int kc = k8 * 8 + tq;
                        const int ar = wm * 16 + g;
                        uint32_t a0 = __float_as_uint(As[ar][kc]);
                        uint32_t a1 = __float_as_uint(As[ar + 8][kc]);
                        uint32_t a2 = __float_as_uint(As[ar][kc + 4]);
                        uint32_t a3 = __float_as_uint(As[ar + 8][kc + 4]);
#pragma unroll
                        for (int j = 0; j < 4; j++) {
                            const int bc = wn * 32 + j * 8 + g;
                            mma8(acc[j], a0, a1, a2, a3,
                                 __float_as_uint(Bs[bc][kc]), __float_as_uint(Bs[bc][kc + 4]));
                        }
                    }
                }
            }

            // dump fragments to Gs
            __syncthreads();
#pragma unroll
            for (int j = 0; j < 4; j++)
#pragma unroll
                for (int d = 0; d < 4; d++) {
                    const int rr = wm * 16 + g + ((d & 2) ? 8 : 0);
                    const int cc = wn * 32 + j * 8 + tq * 2 + (d & 1);
                    Gs[rr][cc] = acc[j][d];
                }
            __syncthreads();

            // elementwise LSTM update
#pragma unroll
            for (int e = 0; e < 4; e++) {
                const int lin = tid + 256 * e;
                const int r = lin >> 5, hc = lin & 31;
                float iG = Gs[r][hc]       + bias_s[l][hc];
                float fG = Gs[r][32 + hc]  + bias_s[l][32 + hc];
                float gG = Gs[r][64 + hc]  + bias_s[l][64 + hc];
                float oG = Gs[r][96 + hc]  + bias_s[l][96 + hc];
                const float cn = sigf(fG) * c_reg[l][e] + sigf(iG) * tanhfast(gG);
                c_reg[l][e] = cn;
                g_h[cur][l][row0 + r][hc0 + hc] = sigf(oG) * tanhfast(cn);
            }
            grid_sync(NBLK);
        }

        // fc: out(t) = h7(t) @ Wfc^T + bfc ; also becomes pred for t+1
        const int r1 = tid >> 3, o1 = tid & 7;
        float po0 = __ldg(&bfc[o1]);
        float po1 = (tid < 32) ? __ldg(&bfc[8]) : 0.f;
        for (int s = 0; s < 2; s++) {
            __syncthreads();
#pragma unroll
            for (int q = 0; q < 4; q++) {
                const int i = tid + 256 * q;
                const int r = i >> 5, cq = (i & 31) << 2;
                float4 v = __ldcg((const float4*)&g_h[cur][7][row0 + r][s * 128 + cq]);
                Gs[r][cq] = v.x; Gs[r][cq + 1] = v.y; Gs[r][cq + 2] = v.z; Gs[r][cq + 3] = v.w;
            }
            __syncthreads();
#pragma unroll 4
            for (int k = 0; k < 128; k++) {
                po0 += Gs[r1][k] * __ldg(&Wfc[o1 * 256 + s * 128 + k]);
                if (tid < 32) po1 += Gs[tid][k] * __ldg(&Wfc[8 * 256 + s * 128 + k]);
            }
        }
        __syncthreads();
        xs[r1][1 + o1] = po0;
        if (tid < 32) xs[tid][9] = po1;
        if (bh == 0) {
            out[(size_t)(row0 + r1) * (NSTEP * 9) + t * 9 + o1] = po0;
            if (tid < 32) out[(size_t)(row0 + tid) * (NSTEP * 9) + t * 9 + 8] = po1;
        }
        __syncthreads();
    }
}

extern "C" void kernel_launch(void* const* d_in, const int* in_sizes, int n_in,
                              void* d_out, int out_size) {
    const float* states = (const float*)d_in[0];
    const float* acts   = (const float*)d_in[1];
    const float* dts    = (const float*)d_in[2];
    const float* W1     = (const float*)d_in[3];
    const float* b1     = (const float*)d_in[4];
    const float* W2     = (const float*)d_in[5];
    const float* b2     = (const float*)d_in[6];
    const float* Wih0   = (const float*)d_in[7];
    const float* Whh0   = (const float*)d_in[8];
    const float* bih0   = (const float*)d_in[9];
    const float* bhh0   = (const float*)d_in[10];
    const float* Wih    = (const float*)d_in[11];
    const float* Whh    = (const float*)d_in[12];
    const float* bih    = (const float*)d_in[13];
    const float* bhh    = (const float*)d_in[14];
    const float* Wfc    = (const float*)d_in[15];
    const float* bfc    = (const float*)d_in[16];
    float* out = (float*)d_out;

    k_gemm1<<<16 * ((MLPH + 127) / 128), 256>>>(states, acts, W1, b1);
    k_gemm2<<<8 * (4096 / 64), 256>>>(W2, b2);
    k_rollout<<<NBLK, 256>>>(states, acts, dts, Wih0, Whh0, bih0, bhh0,
                             Wih, Whh, bih, bhh, Wfc, bfc, out);
}

// round 3
// speedup vs baseline: 1.3357x; 1.3357x over previous
#include <cuda_runtime.h>
#include <math.h>
#include <stdint.h>

#define B_    512
#define T_    76
#define HIST  10
#define H_    256
#define L_    8
#define NSTEP 64
#define MLPH  15000
#define MLPP  15008      // padded row stride for g_mlp
#define K1    130
#define NBLK  128
#define NCH2  469        // gemm2 chunks: 468 full + 1 tail

// ---------------- static device scratch ----------------
__device__ __align__(16) float g_mlp[B_ * MLPP];
__device__ __align__(16) float g_h[2][L_][B_][H_];
__device__ __align__(16) float g_c[L_][B_][H_];
__device__ __align__(16) float g_Wp[8][2][8][8][4096];   // [l][p][bh][kc][c*32+kk]
__device__ __align__(16) float g_Wih0p[8][128 * 16];     // [bh][c*16+k]
__device__ __align__(16) float g_W2tail[4096 * 32];      // last-24 cols of W2, padded
__device__ unsigned g_cnt2[16];

// ---------------- helpers ----------------
__device__ __forceinline__ float tf32f(float x) {
    uint32_t r; asm("cvt.rna.tf32.f32 %0, %1;" : "=r"(r) : "f"(x));
    return __uint_as_float(r);
}
__device__ __forceinline__ void mma8(float c[4], uint32_t a0, uint32_t a1, uint32_t a2, uint32_t a3,
                                     uint32_t b0, uint32_t b1) {
    asm volatile(
        "mma.sync.aligned.m16n8k8.row.col.f32.tf32.tf32.f32 "
        "{%0,%1,%2,%3},{%4,%5,%6,%7},{%8,%9},{%0,%1,%2,%3};\n"
        : "+f"(c[0]), "+f"(c[1]), "+f"(c[2]), "+f"(c[3])
        : "r"(a0), "r"(a1), "r"(a2), "r"(a3), "r"(b0), "r"(b1));
}
__device__ __forceinline__ float sigf(float x) { return __fdividef(1.f, 1.f + __expf(-x)); }
__device__ __forceinline__ float tanhfast(float x) { return 2.f * sigf(2.f * x) - 1.f; }

__device__ __forceinline__ void cpa16(void* s, const void* g) {
    uint32_t sa = (uint32_t)__cvta_generic_to_shared(s);
    asm volatile("cp.async.cg.shared.global [%0], [%1], 16;" :: "r"(sa), "l"(g));
}
#define CP_COMMIT() asm volatile("cp.async.commit_group;\n")
#define CP_WAIT(n)  asm volatile("cp.async.wait_group %0;\n" :: "n"(n))

// warp-tile mma: M32xN128 block tile, 8 warps (2x4), warp tile 16x32
__device__ __forceinline__ void mma_tile(const float (*As)[36], const float (*Bs)[36],
                                         float acc[4][4], int wm, int wn, int g, int tq, int nk8) {
    for (int k8 = 0; k8 < nk8; k8++) {
        const int kc = k8 * 8 + tq;
        const int ar = wm * 16 + g;
        uint32_t a0 = __float_as_uint(As[ar][kc]);
        uint32_t a1 = __float_as_uint(As[ar + 8][kc]);
        uint32_t a2 = __float_as_uint(As[ar][kc + 4]);
        uint32_t a3 = __float_as_uint(As[ar + 8][kc + 4]);
#pragma unroll
        for (int j = 0; j < 4; j++) {
            const int bc = wn * 32 + j * 8 + g;
            mma8(acc[j], a0, a1, a2, a3,
                 __float_as_uint(Bs[bc][kc]), __float_as_uint(Bs[bc][kc + 4]));
        }
    }
}

// ---------------- prep: pack + tf32-round rollout weights ----------------
__global__ void __launch_bounds__(256) k_prep_w(const float* __restrict__ Whh0,
                                                const float* __restrict__ Wih,
                                                const float* __restrict__ Whh) {
    const int idx = blockIdx.x * 256 + threadIdx.x;  // 4194304 total
    const int e = idx & 4095;
    const int kc = (idx >> 12) & 7;
    const int bh = (idx >> 15) & 7;
    const int p = (idx >> 18) & 1;
    const int l = idx >> 19;
    const int c = e >> 5, kk = e & 31;
    const int n = ((c >> 5) << 8) + bh * 32 + (c & 31);
    const int k = kc * 32 + kk;
    float v = 0.f;
    if (l == 0) { if (p == 1) v = Whh0[n * 256 + k]; }
    else v = (p == 0) ? Wih[(size_t)(l - 1) * 262144 + n * 256 + k]
                      : Whh[(size_t)(l - 1) * 262144 + n * 256 + k];
    g_Wp[l][p][bh][kc][e] = tf32f(v);
}

__global__ void __launch_bounds__(256) k_prep_small(const float* __restrict__ Wih0,
                                                    const float* __restrict__ W2) {
    const int i = blockIdx.x * 256 + threadIdx.x;
    if (i < 131072) {                       // W2 tail pack: 4096 rows x 32 (24 valid)
        const int n = i >> 5, kk = i & 31;
        g_W2tail[i] = (kk < 24) ? tf32f(W2[(size_t)n * MLPH + 14976 + kk]) : 0.f;
    } else if (i < 131072 + 16384) {        // Wih0 pack: padded K=16
        const int j = i - 131072;
        const int bh = j >> 11, e = j & 2047;
        const int c = e >> 4, k = e & 15;
        const int n = ((c >> 5) << 8) + bh * 32 + (c & 31);
        g_Wih0p[bh][e] = (k < 14) ? tf32f(Wih0[n * 14 + k]) : 0.f;
    } else if (i < 131072 + 16384 + 4096) { // g_mlp pad zero
        const int j = i - 131072 - 16384;
        g_mlp[(size_t)(j >> 3) * MLPP + MLPH + (j & 7)] = 0.f;
    } else if (i < 131072 + 16384 + 4096 + 16) {
        g_cnt2[i - 131072 - 16384 - 4096] = 0u;
    }
}

// ---------------- GEMM1: mlp = relu(enc @ W1^T + b1), fp32 (tf32-rounded out) ----------------
__global__ void __launch_bounds__(256) k_gemm1(const float* __restrict__ states,
                                               const float* __restrict__ acts,
                                               const float* __restrict__ W1,
                                               const float* __restrict__ b1) {
    const int bm = blockIdx.x & 15;
    const int bn = blockIdx.x >> 4;
    const int n0 = bn * 128;
    const int tid = threadIdx.x;
    __shared__ float enc_s[32][132];
    __shared__ float w_s[128][33];

    for (int i = tid; i < 32 * K1; i += 256) {
        const int r = i / K1, k = i % K1;
        const int b = bm * 32 + r;
        const int tt = k / 13, j = k % 13;
        enc_s[r][k] = (j < 9) ? states[(b * T_ + tt) * 12 + 3 + j]
                              : acts[(b * T_ + tt) * 4 + (j - 9)];
    }

    float acc[4][4];
#pragma unroll
    for (int ii = 0; ii < 4; ii++)
#pragma unroll
        for (int jj = 0; jj < 4; jj++) acc[ii][jj] = 0.f;

    const int tr = tid >> 5;
    const int tc = tid & 31;

    for (int k0 = 0; k0 < K1; k0 += 32) {
        const int kn = min(32, K1 - k0);
        __syncthreads();
        for (int i = tid; i < 128 * 32; i += 256) {
            const int c = i >> 5, kk = i & 31;
            const int n = n0 + c;
            w_s[c][kk] = (kk < kn && n < MLPH) ? W1[n * K1 + k0 + kk] : 0.f;
        }
        __syncthreads();
        for (int kk = 0; kk < kn; kk++) {
            float a[4], w[4];
#pragma unroll
            for (int ii = 0; ii < 4; ii++) a[ii] = enc_s[tr + 8 * ii][k0 + kk];
#pragma unroll
            for (int jj = 0; jj < 4; jj++) w[jj] = w_s[tc + 32 * jj][kk];
#pragma unroll
            for (int ii = 0; ii < 4; ii++)
#pragma unroll
                for (int jj = 0; jj < 4; jj++) acc[ii][jj] += a[ii] * w[jj];
        }
    }
#pragma unroll
    for (int ii = 0; ii < 4; ii++)
#pragma unroll
        for (int jj = 0; jj < 4; jj++) {
            const int b = bm * 32 + tr + 8 * ii;
            const int n = n0 + tc + 32 * jj;
            if (n < MLPH) g_mlp[(size_t)b * MLPP + n] = tf32f(fmaxf(acc[ii][jj] + b1[n], 0.f));
        }
}

// ---------------- GEMM2: hc = mlp @ W2^T + b2 (cp.async 2-stage pipeline) ----------------
__global__ void __launch_bounds__(256) k_gemm2(const float* __restrict__ W2,
                                               const float* __restrict__ b2) {
    const int bm = blockIdx.x & 7;
    const int bn = blockIdx.x >> 3;
    const int tid = threadIdx.x;
    const int warp = tid >> 5, lane = tid & 31;
    const int wm = warp >> 1, wn = warp & 1;
    const int g = lane >> 2, tq = lane & 3;

    __shared__ __align__(16) float As[2][64][36];
    __shared__ __align__(16) float Bs[2][64][36];

    float acc[4][4];
#pragma unroll
    for (int j = 0; j < 4; j++)
#pragma unroll
        for (int d = 0; d < 4; d++) acc[j][d] = 0.f;

    // stage lambda inlined
    auto stage = [&](int buf, int c) {
        const int k0 = c * 32;
#pragma unroll
        for (int q = 0; q < 2; q++) {
            const int s = tid + q * 256;
            const int r = s >> 3, kq = (s & 7) << 2;
            cpa16(&As[buf][r][kq], &g_mlp[(size_t)(bm * 64 + r) * MLPP + k0 + kq]);
            const float* bsrc = (c < 468) ? (W2 + (size_t)(bn * 64 + r) * MLPH + k0 + kq)
                                          : (&g_W2tail[(bn * 64 + r) * 32 + kq]);
            cpa16(&Bs[buf][r][kq], bsrc);
        }
        CP_COMMIT();
    };

    stage(0, 0);
    for (int c = 0; c < NCH2; c++) {
        if (c + 1 < NCH2) { stage((c + 1) & 1, c + 1); CP_WAIT(1); }
        else { CP_WAIT(0); }
        __syncthreads();
        const int buf = c & 1;
#pragma unroll
        for (int k8 = 0; k8 < 4; k8++) {
            const int kc = k8 * 8 + tq;
            const int ar = wm * 16 + g;
            uint32_t a0 = __float_as_uint(As[buf][ar][kc]);
            uint32_t a1 = __float_as_uint(As[buf][ar + 8][kc]);
            uint32_t a2 = __float_as_uint(As[buf][ar][kc + 4]);
            uint32_t a3 = __float_as_uint(As[buf][ar + 8][kc + 4]);
#pragma unroll
            for (int j = 0; j < 4; j++) {
                const int bc = wn * 32 + j * 8 + g;
                mma8(acc[j], a0, a1, a2, a3,
                     __float_as_uint(Bs[buf][bc][kc]), __float_as_uint(Bs[buf][bc][kc + 4]));
            }
        }
        __syncthreads();
    }
#pragma unroll
    for (int j = 0; j < 4; j++)
#pragma unroll
        for (int d = 0; d < 4; d++) {
            const int r = wm * 16 + g + ((d & 2) ? 8 : 0);
            const int c = wn * 32 + j * 8 + tq * 2 + (d & 1);
            const int b = bm * 64 + r;
            const int n = bn * 64 + c;
            const float v = acc[j][d] + b2[n];
            const int l = n >> 9, rem = n & 511;
            if (rem < H_) g_h[1][l][b][rem] = v;
            else          g_c[l][b][rem - H_] = v;
        }
}

// ---------------- rollout: persistent, per-rowgroup sync, cp.async pipeline ----------------
struct RollSmem {
    float As[2][32][36];
    float Bs[2][128][36];
    float Gs[32][132];
    float xs[32][16];
    float bias[8][128];
};

__global__ void __launch_bounds__(256) k_rollout(
    const float* __restrict__ states, const float* __restrict__ acts,
    const float* __restrict__ dts,
    const float* __restrict__ bih0, const float* __restrict__ bhh0,
    const float* __restrict__ bih, const float* __restrict__ bhh,
    const float* __restrict__ Wfc, const float* __restrict__ bfc,
    float* __restrict__ out)
{
    const int bm = blockIdx.x >> 3;
    const int bh = blockIdx.x & 7;
    const int tid = threadIdx.x;
    const int warp = tid >> 5, lane = tid & 31;
    const int wm = warp >> 2, wn = warp & 3;
    const int g = lane >> 2, tq = lane & 3;
    const int row0 = bm * 32;
    const int hc0 = bh * 32;

    extern __shared__ __align__(16) float smem_raw[];
    RollSmem* sm = (RollSmem*)smem_raw;

    // biases
    for (int i = tid; i < 1024; i += 256) {
        const int l = i >> 7;
        const int gate = (i >> 5) & 3;
        const int hc = i & 31;
        const int n = gate * 256 + hc0 + hc;
        float v;
        if (l == 0) v = __ldg(&bih0[n]) + __ldg(&bhh0[n]);
        else        v = __ldg(&bih[(l - 1) * 1024 + n]) + __ldg(&bhh[(l - 1) * 1024 + n]);
        sm->bias[l][gate * 32 + hc] = v;
    }
    // c0
    float c_reg[8][4];
#pragma unroll
    for (int l = 0; l < 8; l++)
#pragma unroll
        for (int e = 0; e < 4; e++) {
            const int lin = tid + 256 * e;
            const int r = lin >> 5, hc = lin & 31;
            c_reg[l][e] = __ldcg(&g_c[l][row0 + r][hc0 + hc]);
        }
    // pred0 + pad
    {
        const int r = tid >> 3, j = tid & 7;
        sm->xs[r][1 + j] = states[((row0 + r) * T_ + HIST) * 12 + 3 + j];
        if (tid < 32) sm->xs[tid][9] = states[((row0 + tid) * T_ + HIST) * 12 + 11];
        if (tid < 32) { sm->xs[tid][14] = 0.f; sm->xs[tid][15] = 0.f; }
    }
    __syncthreads();

    for (int t = 0; t < NSTEP; t++) {
        const int cur = t & 1, old = cur ^ 1;
        if (tid < 32)  sm->xs[tid][0] = dts[(row0 + tid) * T_ + HIST + 1 + t];
        if (tid < 128) {
            const int r = tid >> 2, j = tid & 3;
            sm->xs[r][10 + j] = acts[((row0 + r) * T_ + HIST + t) * 4 + j];
        }
        __syncthreads();

        for (int l = 0; l < 8; l++) {
            const unsigned epoch = (unsigned)(t * 8 + l);
            // wait for (t, l-1) complete by all 8 col-blocks of this row group
            if (epoch) {
                if (tid == 0) {
                    const unsigned tgt = 8u * epoch;
                    while (*(volatile unsigned*)&g_cnt2[bm] < tgt) __nanosleep(32);
                }
                __syncthreads();
            }

            float acc[4][4];
#pragma unroll
            for (int j = 0; j < 4; j++)
#pragma unroll
                for (int d = 0; d < 4; d++) acc[j][d] = 0.f;

            // layer 0: K=16 x-tile
            if (l == 0) {
#pragma unroll
                for (int q = 0; q < 2; q++) {
                    const int e = tid * 4 + q * 1024;
                    const int c = e >> 4, kk = e & 15;
                    cpa16(&sm->Bs[0][c][kk], &g_Wih0p[bh][e]);
                }
                CP_COMMIT();
                {
                    const int e = tid * 2;
                    const int r = e >> 4, k = e & 15;
                    sm->As[0][r][k]     = tf32f(sm->xs[r][k]);
                    sm->As[0][r][k + 1] = tf32f(sm->xs[r][k + 1]);
                }
                CP_WAIT(0);
                __syncthreads();
                mma_tile(sm->As[0], sm->Bs[0], acc, wm, wn, g, tq, 2);
                __syncthreads();
            }

            // K=256 passes (pipelined)
            const int p_first = (l == 0) ? 1 : 0;
            for (int p = p_first; p < 2; p++) {
                const float* hsrc;
                if (l == 0) hsrc = &g_h[old][0][row0][0];
                else if (p == 0) hsrc = &g_h[cur][l - 1][row0][0];
                else hsrc = &g_h[old][l][row0][0];
                const float* wbase = &g_Wp[l][p][bh][0][0];

                // stage chunk 0
                {
                    const int r = tid >> 3, kq = (tid & 7) << 2;
                    cpa16(&sm->As[0][r][kq], hsrc + r * 256 + kq);
#pragma unroll
                    for (int q = 0; q < 4; q++) {
                        const int e = tid * 4 + q * 1024;
                        cpa16(&sm->Bs[0][e >> 5][e & 31], wbase + e);
                    }
                    CP_COMMIT();
                }
                for (int kc = 0; kc < 8; kc++) {
                    if (kc < 7) {
                        const int nb = (kc + 1) & 1;
                        const int k0 = (kc + 1) * 32;
                        const int r = tid >> 3, kq = (tid & 7) << 2;
                        cpa16(&sm->As[nb][r][kq], hsrc + r * 256 + k0 + kq);
                        const float* wt = wbase + (kc + 1) * 4096;
#pragma unroll
                        for (int q = 0; q < 4; q++) {
                            const int e = tid * 4 + q * 1024;
                            cpa16(&sm->Bs[nb][e >> 5][e & 31], wt + e);
                        }
                        CP_COMMIT();
                        CP_WAIT(1);
                    } else {
                        CP_WAIT(0);
                    }
                    __syncthreads();
                    mma_tile(sm->As[kc & 1], sm->Bs[kc & 1], acc, wm, wn, g, tq, 4);
                    __syncthreads();
                }
            }

            // gates -> smem
#pragma unroll
            for (int j = 0; j < 4; j++)
#pragma unroll
                for (int d = 0; d < 4; d++) {
                    const int rr = wm * 16 + g + ((d & 2) ? 8 : 0);
                    const int cc = wn * 32 + j * 8 + tq * 2 + (d & 1);
                    sm->Gs[rr][cc] = acc[j][d];
                }
            __syncthreads();

            // elementwise update
#pragma unroll
            for (int e = 0; e < 4; e++) {
                const int lin = tid + 256 * e;
                const int r = lin >> 5, hc = lin & 31;
                float iG = sm->Gs[r][hc]      + sm->bias[l][hc];
                float fG = sm->Gs[r][32 + hc] + sm->bias[l][32 + hc];
                float gG = sm->Gs[r][64 + hc] + sm->bias[l][64 + hc];
                float oG = sm->Gs[r][96 + hc] + sm->bias[l][96 + hc];
                const float cn = sigf(fG) * c_reg[l][e] + sigf(iG) * tanhfast(gG);
                c_reg[l][e] = cn;
                g_h[cur][l][row0 + r][hc0 + hc] = tf32f(sigf(oG) * tanhfast(cn));
            }
            __threadfence();
            __syncthreads();
            if (tid == 0) atomicAdd(&g_cnt2[bm], 1u);
        }

        // wait for layer 7 of this rowgroup
        if (tid == 0) {
            const unsigned tgt = 8u * (unsigned)(t * 8 + 8);
            while (*(volatile unsigned*)&g_cnt2[bm] < tgt) __nanosleep(32);
        }
        __syncthreads();

        // fc
        const int r1 = tid >> 3, o1 = tid & 7;
        float po0 = __ldg(&bfc[o1]);
        float po1 = (tid < 32) ? __ldg(&bfc[8]) : 0.f;
        for (int s = 0; s < 2; s++) {
            __syncthreads();
#pragma unroll
            for (int q = 0; q < 4; q++) {
                const int i = tid + 256 * q;
                const int r = i >> 5, cq = (i & 31) << 2;
                float4 v = __ldcg((const float4*)&g_h[cur][7][row0 + r][s * 128 + cq]);
                sm->Gs[r][cq] = v.x; sm->Gs[r][cq + 1] = v.y;
                sm->Gs[r][cq + 2] = v.z; sm->Gs[r][cq + 3] = v.w;
            }
            __syncthreads();
#pragma unroll 4
            for (int k = 0; k < 128; k++) {
                po0 += sm->Gs[r1][k] * __ldg(&Wfc[o1 * 256 + s * 128 + k]);
                if (tid < 32) po1 += sm->Gs[tid][k] * __ldg(&Wfc[8 * 256 + s * 128 + k]);
            }
        }
        __syncthreads();
        sm->xs[r1][1 + o1] = po0;
        if (tid < 32) sm->xs[tid][9] = po1;
        if (bh == 0) {
            out[(size_t)(row0 + r1) * (NSTEP * 9) + t * 9 + o1] = po0;
            if (tid < 32) out[(size_t)(row0 + tid) * (NSTEP * 9) + t * 9 + 8] = po1;
        }
        __syncthreads();
    }
}

extern "C" void kernel_launch(void* const* d_in, const int* in_sizes, int n_in,
                              void* d_out, int out_size) {
    const float* states = (const float*)d_in[0];
    const float* acts   = (const float*)d_in[1];
    const float* dts    = (const float*)d_in[2];
    const float* W1     = (const float*)d_in[3];
    const float* b1     = (const float*)d_in[4];
    const float* W2     = (const float*)d_in[5];
    const float* b2     = (const float*)d_in[6];
    const float* Wih0   = (const float*)d_in[7];
    const float* Whh0   = (const float*)d_in[8];
    const float* bih0   = (const float*)d_in[9];
    const float* bhh0   = (const float*)d_in[10];
    const float* Wih    = (const float*)d_in[11];
    const float* Whh    = (const float*)d_in[12];
    const float* bih    = (const float*)d_in[13];
    const float* bhh    = (const float*)d_in[14];
    const float* Wfc    = (const float*)d_in[15];
    const float* bfc    = (const float*)d_in[16];
    float* out = (float*)d_out;

    const int smem_bytes = (int)sizeof(RollSmem);
    cudaFuncSetAttribute(k_rollout, cudaFuncAttributeMaxDynamicSharedMemorySize, smem_bytes);

    k_prep_w<<<16384, 256>>>(Whh0, Wih, Whh);
    k_prep_small<<<((131072 + 16384 + 4096 + 16) + 255) / 256, 256>>>(Wih0, W2);
    k_gemm1<<<16 * ((MLPH + 127) / 128), 256>>>(states, acts, W1, b1);
    k_gemm2<<<8 * (4096 / 64), 256>>>(W2, b2);
    k_rollout<<<NBLK, 256, smem_bytes>>>(states, acts, dts, bih0, bhh0,
                                         bih, bhh, Wfc, bfc, out);
}

// round 4
// speedup vs baseline: 1.3360x; 1.0002x over previous
#include <cuda_runtime.h>
#include <math.h>
#include <stdint.h>

#define B_    512
#define T_    76
#define HIST  10
#define H_    256
#define L_    8
#define NSTEP 64
#define MLPH  15000
#define MLPP  15008      // padded row stride for g_mlp
#define K1    130
#define NBLK  128
#define NCH2  469        // gemm2 chunks: 468 full + 1 tail

// ---------------- static device scratch ----------------
__device__ __align__(16) float g_mlp[B_ * MLPP];
__device__ __align__(16) float g_h[2][L_][B_][H_];
__device__ __align__(16) float g_c[L_][B_][H_];
__device__ __align__(16) float g_Wp[8][2][8][8][4096];   // [l][p][bh][kc][c*32+kk]
__device__ __align__(16) float g_Wih0p[8][128 * 16];     // [bh][c*16+k]
__device__ __align__(16) float g_W2tail[4096 * 32];      // last-24 cols of W2, padded
__device__ unsigned g_cnt2[16];

// ---------------- helpers ----------------
__device__ __forceinline__ float tf32f(float x) {
    uint32_t r; asm("cvt.rna.tf32.f32 %0, %1;" : "=r"(r) : "f"(x));
    return __uint_as_float(r);
}
__device__ __forceinline__ void mma8(float c[4], uint32_t a0, uint32_t a1, uint32_t a2, uint32_t a3,
                                     uint32_t b0, uint32_t b1) {
    asm volatile(
        "mma.sync.aligned.m16n8k8.row.col.f32.tf32.tf32.f32 "
        "{%0,%1,%2,%3},{%4,%5,%6,%7},{%8,%9},{%0,%1,%2,%3};\n"
        : "+f"(c[0]), "+f"(c[1]), "+f"(c[2]), "+f"(c[3])
        : "r"(a0), "r"(a1), "r"(a2), "r"(a3), "r"(b0), "r"(b1));
}
__device__ __forceinline__ float sigf(float x) { return __fdividef(1.f, 1.f + __expf(-x)); }
__device__ __forceinline__ float tanhfast(float x) { return 2.f * sigf(2.f * x) - 1.f; }

__device__ __forceinline__ void cpa16(void* s, const void* g) {
    uint32_t sa = (uint32_t)__cvta_generic_to_shared(s);
    asm volatile("cp.async.cg.shared.global [%0], [%1], 16;" :: "r"(sa), "l"(g));
}
#define CP_COMMIT() asm volatile("cp.async.commit_group;\n")
#define CP_WAIT(n)  asm volatile("cp.async.wait_group %0;\n" :: "n"(n))

// warp-tile mma: M32xN128 block tile, 8 warps (2x4), warp tile 16x32
__device__ __forceinline__ void mma_tile(const float (*As)[36], const float (*Bs)[36],
                                         float acc[4][4], int wm, int wn, int g, int tq, int nk8) {
    for (int k8 = 0; k8 < nk8; k8++) {
        const int kc = k8 * 8 + tq;
        const int ar = wm * 16 + g;
        uint32_t a0 = __float_as_uint(As[ar][kc]);
        uint32_t a1 = __float_as_uint(As[ar + 8][kc]);
        uint32_t a2 = __float_as_uint(As[ar][kc + 4]);
        uint32_t a3 = __float_as_uint(As[ar + 8][kc + 4]);
#pragma unroll
        for (int j = 0; j < 4; j++) {
            const int bc = wn * 32 + j * 8 + g;
            mma8(acc[j], a0, a1, a2, a3,
                 __float_as_uint(Bs[bc][kc]), __float_as_uint(Bs[bc][kc + 4]));
        }
    }
}

// ---------------- prep: pack + tf32-round rollout weights ----------------
__global__ void __launch_bounds__(256) k_prep_w(const float* __restrict__ Whh0,
                                                const float* __restrict__ Wih,
                                                const float* __restrict__ Whh) {
    const int idx = blockIdx.x * 256 + threadIdx.x;  // 4194304 total
    const int e = idx & 4095;
    const int kc = (idx >> 12) & 7;
    const int bh = (idx >> 15) & 7;
    const int p = (idx >> 18) & 1;
    const int l = idx >> 19;
    const int c = e >> 5, kk = e & 31;
    const int n = ((c >> 5) << 8) + bh * 32 + (c & 31);
    const int k = kc * 32 + kk;
    float v = 0.f;
    if (l == 0) { if (p == 1) v = Whh0[n * 256 + k]; }
    else v = (p == 0) ? Wih[(size_t)(l - 1) * 262144 + n * 256 + k]
                      : Whh[(size_t)(l - 1) * 262144 + n * 256 + k];
    g_Wp[l][p][bh][kc][e] = tf32f(v);
}

__global__ void __launch_bounds__(256) k_prep_small(const float* __restrict__ Wih0,
                                                    const float* __restrict__ W2) {
    const int i = blockIdx.x * 256 + threadIdx.x;
    if (i < 131072) {                       // W2 tail pack: 4096 rows x 32 (24 valid)
        const int n = i >> 5, kk = i & 31;
        g_W2tail[i] = (kk < 24) ? tf32f(W2[(size_t)n * MLPH + 14976 + kk]) : 0.f;
    } else if (i < 131072 + 16384) {        // Wih0 pack: padded K=16
        const int j = i - 131072;
        const int bh = j >> 11, e = j & 2047;
        const int c = e >> 4, k = e & 15;
        const int n = ((c >> 5) << 8) + bh * 32 + (c & 31);
        g_Wih0p[bh][e] = (k < 14) ? tf32f(Wih0[n * 14 + k]) : 0.f;
    } else if (i < 131072 + 16384 + 4096) { // g_mlp pad zero
        const int j = i - 131072 - 16384;
        g_mlp[(size_t)(j >> 3) * MLPP + MLPH + (j & 7)] = 0.f;
    } else if (i < 131072 + 16384 + 4096 + 16) {
        g_cnt2[i - 131072 - 16384 - 4096] = 0u;
    }
}

// ---------------- GEMM1: mlp = relu(enc @ W1^T + b1), fp32 (tf32-rounded out) ----------------
__global__ void __launch_bounds__(256) k_gemm1(const float* __restrict__ states,
                                               const float* __restrict__ acts,
                                               const float* __restrict__ W1,
                                               const float* __restrict__ b1) {
    const int bm = blockIdx.x & 15;
    const int bn = blockIdx.x >> 4;
    const int n0 = bn * 128;
    const int tid = threadIdx.x;
    __shared__ float enc_s[32][132];
    __shared__ float w_s[128][33];

    for (int i = tid; i < 32 * K1; i += 256) {
        const int r = i / K1, k = i % K1;
        const int b = bm * 32 + r;
        const int tt = k / 13, j = k % 13;
        enc_s[r][k] = (j < 9) ? states[(b * T_ + tt) * 12 + 3 + j]
                              : acts[(b * T_ + tt) * 4 + (j - 9)];
    }

    float acc[4][4];
#pragma unroll
    for (int ii = 0; ii < 4; ii++)
#pragma unroll
        for (int jj = 0; jj < 4; jj++) acc[ii][jj] = 0.f;

    const int tr = tid >> 5;
    const int tc = tid & 31;

    for (int k0 = 0; k0 < K1; k0 += 32) {
        const int kn = min(32, K1 - k0);
        __syncthreads();
        for (int i = tid; i < 128 * 32; i += 256) {
            const int c = i >> 5, kk = i & 31;
            const int n = n0 + c;
            w_s[c][kk] = (kk < kn && n < MLPH) ? W1[n * K1 + k0 + kk] : 0.f;
        }
        __syncthreads();
        for (int kk = 0; kk < kn; kk++) {
            float a[4], w[4];
#pragma unroll
            for (int ii = 0; ii < 4; ii++) a[ii] = enc_s[tr + 8 * ii][k0 + kk];
#pragma unroll
            for (int jj = 0; jj < 4; jj++) w[jj] = w_s[tc + 32 * jj][kk];
#pragma unroll
            for (int ii = 0; ii < 4; ii++)
#pragma unroll
                for (int jj = 0; jj < 4; jj++) acc[ii][jj] += a[ii] * w[jj];
        }
    }
#pragma unroll
    for (int ii = 0; ii < 4; ii++)
#pragma unroll
        for (int jj = 0; jj < 4; jj++) {
            const int b = bm * 32 + tr + 8 * ii;
            const int n = n0 + tc + 32 * jj;
            if (n < MLPH) g_mlp[(size_t)b * MLPP + n] = tf32f(fmaxf(acc[ii][jj] + b1[n], 0.f));
        }
}

// ---------------- GEMM2: hc = mlp @ W2^T + b2 (cp.async 2-stage pipeline) ----------------
__global__ void __launch_bounds__(256) k_gemm2(const float* __restrict__ W2,
                                               const float* __restrict__ b2) {
    const int bm = blockIdx.x & 7;
    const int bn = blockIdx.x >> 3;
    const int tid = threadIdx.x;
    const int warp = tid >> 5, lane = tid & 31;
    const int wm = warp >> 1, wn = warp & 1;
    const int g = lane >> 2, tq = lane & 3;

    __shared__ __align__(16) float As[2][64][36];
    __shared__ __align__(16) float Bs[2][64][36];

    float acc[4][4];
#pragma unroll
    for (int j = 0; j < 4; j++)
#pragma unroll
        for (int d = 0; d < 4; d++) acc[j][d] = 0.f;

    // stage lambda inlined
    auto stage = [&](int buf, int c) {
        const int k0 = c * 32;
#pragma unroll
        for (int q = 0; q < 2; q++) {
            const int s = tid + q * 256;
            const int r = s >> 3, kq = (s & 7) << 2;
            cpa16(&As[buf][r][kq], &g_mlp[(size_t)(bm * 64 + r) * MLPP + k0 + kq]);
            const float* bsrc = (c < 468) ? (W2 + (size_t)(bn * 64 + r) * MLPH + k0 + kq)
                                          : (&g_W2tail[(bn * 64 + r) * 32 + kq]);
            cpa16(&Bs[buf][r][kq], bsrc);
        }
        CP_COMMIT();
    };

    stage(0, 0);
    for (int c = 0; c < NCH2; c++) {
        if (c + 1 < NCH2) { stage((c + 1) & 1, c + 1); CP_WAIT(1); }
        else { CP_WAIT(0); }
        __syncthreads();
        const int buf = c & 1;
#pragma unroll
        for (int k8 = 0; k8 < 4; k8++) {
            const int kc = k8 * 8 + tq;
            const int ar = wm * 16 + g;
            uint32_t a0 = __float_as_uint(As[buf][ar][kc]);
            uint32_t a1 = __float_as_uint(As[buf][ar + 8][kc]);
            uint32_t a2 = __float_as_uint(As[buf][ar][kc + 4]);
            uint32_t a3 = __float_as_uint(As[buf][ar + 8][kc + 4]);
#pragma unroll
            for (int j = 0; j < 4; j++) {
                const int bc = wn * 32 + j * 8 + g;
                mma8(acc[j], a0, a1, a2, a3,
                     __float_as_uint(Bs[buf][bc][kc]), __float_as_uint(Bs[buf][bc][kc + 4]));
            }
        }
        __syncthreads();
    }
#pragma unroll
    for (int j = 0; j < 4; j++)
#pragma unroll
        for (int d = 0; d < 4; d++) {
            const int r = wm * 16 + g + ((d & 2) ? 8 : 0);
            const int c = wn * 32 + j * 8 + tq * 2 + (d & 1);
            const int b = bm * 64 + r;
            const int n = bn * 64 + c;
            const float v = acc[j][d] + b2[n];
            const int l = n >> 9, rem = n & 511;
            if (rem < H_) g_h[1][l][b][rem] = v;
            else          g_c[l][b][rem - H_] = v;
        }
}

// ---------------- rollout: persistent, per-rowgroup sync, cp.async pipeline ----------------
struct RollSmem {
    float As[2][32][36];
    float Bs[2][128][36];
    float Gs[32][132];
    float xs[32][16];
    float bias[8][128];
};

__global__ void __launch_bounds__(256) k_rollout(
    const float* __restrict__ states, const float* __restrict__ acts,
    const float* __restrict__ dts,
    const float* __restrict__ bih0, const float* __restrict__ bhh0,
    const float* __restrict__ bih, const float* __restrict__ bhh,
    const float* __restrict__ Wfc, const float* __restrict__ bfc,
    float* __restrict__ out)
{
    const int bm = blockIdx.x >> 3;
    const int bh = blockIdx.x & 7;
    const int tid = threadIdx.x;
    const int warp = tid >> 5, lane = tid & 31;
    const int wm = warp >> 2, wn = warp & 3;
    const int g = lane >> 2, tq = lane & 3;
    const int row0 = bm * 32;
    const int hc0 = bh * 32;

    extern __shared__ __align__(16) float smem_raw[];
    RollSmem* sm = (RollSmem*)smem_raw;

    // biases
    for (int i = tid; i < 1024; i += 256) {
        const int l = i >> 7;
        const int gate = (i >> 5) & 3;
        const int hc = i & 31;
        const int n = gate * 256 + hc0 + hc;
        float v;
        if (l == 0) v = __ldg(&bih0[n]) + __ldg(&bhh0[n]);
        else        v = __ldg(&bih[(l - 1) * 1024 + n]) + __ldg(&bhh[(l - 1) * 1024 + n]);
        sm->bias[l][gate * 32 + hc] = v;
    }
    // c0
    float c_reg[8][4];
#pragma unroll
    for (int l = 0; l < 8; l++)
#pragma unroll
        for (int e = 0; e < 4; e++) {
            const int lin = tid + 256 * e;
            const int r = lin >> 5, hc = lin & 31;
            c_reg[l][e] = __ldcg(&g_c[l][row0 + r][hc0 + hc]);
        }
    // pred0 + pad
    {
        const int r = tid >> 3, j = tid & 7;
        sm->xs[r][1 + j] = states[((row0 + r) * T_ + HIST) * 12 + 3 + j];
        if (tid < 32) sm->xs[tid][9] = states[((row0 + tid) * T_ + HIST) * 12 + 11];
        if (tid < 32) { sm->xs[tid][14] = 0.f; sm->xs[tid][15] = 0.f; }
    }
    __syncthreads();

    for (int t = 0; t < NSTEP; t++) {
        const int cur = t & 1, old = cur ^ 1;
        if (tid < 32)  sm->xs[tid][0] = dts[(row0 + tid) * T_ + HIST + 1 + t];
        if (tid < 128) {
            const int r = tid >> 2, j = tid & 3;
            sm->xs[r][10 + j] = acts[((row0 + r) * T_ + HIST + t) * 4 + j];
        }
        __syncthreads();

        for (int l = 0; l < 8; l++) {
            const unsigned epoch = (unsigned)(t * 8 + l);
            // wait for (t, l-1) complete by all 8 col-blocks of this row group
            if (epoch) {
                if (tid == 0) {
                    const unsigned tgt = 8u * epoch;
                    while (*(volatile unsigned*)&g_cnt2[bm] < tgt) __nanosleep(32);
                }
                __syncthreads();
            }

            float acc[4][4];
#pragma unroll
            for (int j = 0; j < 4; j++)
#pragma unroll
                for (int d = 0; d < 4; d++) acc[j][d] = 0.f;

            // layer 0: K=16 x-tile
            if (l == 0) {
#pragma unroll
                for (int q = 0; q < 2; q++) {
                    const int e = tid * 4 + q * 1024;
                    const int c = e >> 4, kk = e & 15;
                    cpa16(&sm->Bs[0][c][kk], &g_Wih0p[bh][e]);
                }
                CP_COMMIT();
                {
                    const int e = tid * 2;
                    const int r = e >> 4, k = e & 15;
                    sm->As[0][r][k]     = tf32f(sm->xs[r][k]);
                    sm->As[0][r][k + 1] = tf32f(sm->xs[r][k + 1]);
                }
                CP_WAIT(0);
                __syncthreads();
                mma_tile(sm->As[0], sm->Bs[0], acc, wm, wn, g, tq, 2);
                __syncthreads();
            }

            // K=256 passes (pipelined)
            const int p_first = (l == 0) ? 1 : 0;
            for (int p = p_first; p < 2; p++) {
                const float* hsrc;
                if (l == 0) hsrc = &g_h[old][0][row0][0];
                else if (p == 0) hsrc = &g_h[cur][l - 1][row0][0];
                else hsrc = &g_h[old][l][row0][0];
                const float* wbase = &g_Wp[l][p][bh][0][0];

                // stage chunk 0
                {
                    const int r = tid >> 3, kq = (tid & 7) << 2;
                    cpa16(&sm->As[0][r][kq], hsrc + r * 256 + kq);
#pragma unroll
                    for (int q = 0; q < 4; q++) {
                        const int e = tid * 4 + q * 1024;
                        cpa16(&sm->Bs[0][e >> 5][e & 31], wbase + e);
                    }
                    CP_COMMIT();
                }
                for (int kc = 0; kc < 8; kc++) {
                    if (kc < 7) {
                        const int nb = (kc + 1) & 1;
                        const int k0 = (kc + 1) * 32;
                        const int r = tid >> 3, kq = (tid & 7) << 2;
                        cpa16(&sm->As[nb][r][kq], hsrc + r * 256 + k0 + kq);
                        const float* wt = wbase + (kc + 1) * 4096;
#pragma unroll
                        for (int q = 0; q < 4; q++) {
                            const int e = tid * 4 + q * 1024;
                            cpa16(&sm->Bs[nb][e >> 5][e & 31], wt + e);
                        }
                        CP_COMMIT();
                        CP_WAIT(1);
                    } else {
                        CP_WAIT(0);
                    }
                    __syncthreads();
                    mma_tile(sm->As[kc & 1], sm->Bs[kc & 1], acc, wm, wn, g, tq, 4);
                    __syncthreads();
                }
            }

            // gates -> smem
#pragma unroll
            for (int j = 0; j < 4; j++)
#pragma unroll
                for (int d = 0; d < 4; d++) {
                    const int rr = wm * 16 + g + ((d & 2) ? 8 : 0);
                    const int cc = wn * 32 + j * 8 + tq * 2 + (d & 1);
                    sm->Gs[rr][cc] = acc[j][d];
                }
            __syncthreads();

            // elementwise update
#pragma unroll
            for (int e = 0; e < 4; e++) {
                const int lin = tid + 256 * e;
                const int r = lin >> 5, hc = lin & 31;
                float iG = sm->Gs[r][hc]      + sm->bias[l][hc];
                float fG = sm->Gs[r][32 + hc] + sm->bias[l][32 + hc];
                float gG = sm->Gs[r][64 + hc] + sm->bias[l][64 + hc];
                float oG = sm->Gs[r][96 + hc] + sm->bias[l][96 + hc];
                const float cn = sigf(fG) * c_reg[l][e] + sigf(iG) * tanhfast(gG);
                c_reg[l][e] = cn;
                g_h[cur][l][row0 + r][hc0 + hc] = tf32f(sigf(oG) * tanhfast(cn));
            }
            __threadfence();
            __syncthreads();
            if (tid == 0) atomicAdd(&g_cnt2[bm], 1u);
        }

        // wait for layer 7 of this rowgroup
        if (tid == 0) {
            const unsigned tgt = 8u * (unsigned)(t * 8 + 8);
            while (*(volatile unsigned*)&g_cnt2[bm] < tgt) __nanosleep(32);
        }
        __syncthreads();

        // fc
        const int r1 = tid >> 3, o1 = tid & 7;
        float po0 = __ldg(&bfc[o1]);
        float po1 = (tid < 32) ? __ldg(&bfc[8]) : 0.f;
        for (int s = 0; s < 2; s++) {
            __syncthreads();
#pragma unroll
            for (int q = 0; q < 4; q++) {
                const int i = tid + 256 * q;
                const int r = i >> 5, cq = (i & 31) << 2;
                float4 v = __ldcg((const float4*)&g_h[cur][7][row0 + r][s * 128 + cq]);
                sm->Gs[r][cq] = v.x; sm->Gs[r][cq + 1] = v.y;
                sm->Gs[r][cq + 2] = v.z; sm->Gs[r][cq + 3] = v.w;
            }
            __syncthreads();
#pragma unroll 4
            for (int k = 0; k < 128; k++) {
                po0 += sm->Gs[r1][k] * __ldg(&Wfc[o1 * 256 + s * 128 + k]);
                if (tid < 32) po1 += sm->Gs[tid][k] * __ldg(&Wfc[8 * 256 + s * 128 + k]);
            }
        }
        __syncthreads();
        sm->xs[r1][1 + o1] = po0;
        if (tid < 32) sm->xs[tid][9] = po1;
        if (bh == 0) {
            out[(size_t)(row0 + r1) * (NSTEP * 9) + t * 9 + o1] = po0;
            if (tid < 32) out[(size_t)(row0 + tid) * (NSTEP * 9) + t * 9 + 8] = po1;
        }
        __syncthreads();
    }
}

extern "C" void kernel_launch(void* const* d_in, const int* in_sizes, int n_in,
                              void* d_out, int out_size) {
    const float* states = (const float*)d_in[0];
    const float* acts   = (const float*)d_in[1];
    const float* dts    = (const float*)d_in[2];
    const float* W1     = (const float*)d_in[3];
    const float* b1     = (const float*)d_in[4];
    const float* W2     = (const float*)d_in[5];
    const float* b2     = (const float*)d_in[6];
    const float* Wih0   = (const float*)d_in[7];
    const float* Whh0   = (const float*)d_in[8];
    const float* bih0   = (const float*)d_in[9];
    const float* bhh0   = (const float*)d_in[10];
    const float* Wih    = (const float*)d_in[11];
    const float* Whh    = (const float*)d_in[12];
    const float* bih    = (const float*)d_in[13];
    const float* bhh    = (const float*)d_in[14];
    const float* Wfc    = (const float*)d_in[15];
    const float* bfc    = (const float*)d_in[16];
    float* out = (float*)d_out;

    const int smem_bytes = (int)sizeof(RollSmem);
    cudaFuncSetAttribute(k_rollout, cudaFuncAttributeMaxDynamicSharedMemorySize, smem_bytes);

    k_prep_w<<<16384, 256>>>(Whh0, Wih, Whh);
    k_prep_small<<<((131072 + 16384 + 4096 + 16) + 255) / 256, 256>>>(Wih0, W2);
    k_gemm1<<<16 * ((MLPH + 127) / 128), 256>>>(states, acts, W1, b1);
    k_gemm2<<<8 * (4096 / 64), 256>>>(W2, b2);
    k_rollout<<<NBLK, 256, smem_bytes>>>(states, acts, dts, bih0, bhh0,
                                         bih, bhh, Wfc, bfc, out);
}

// round 5
// speedup vs baseline: 1.7777x; 1.3307x over previous
#include <cuda_runtime.h>
#include <stdint.h>

#define B_    512
#define T_    76
#define HIST  10
#define H_    256
#define L_    8
#define NSTEP 64
#define MLPH  15000
#define MLPP  15008
#define K1    130
#define NCH2  469

__device__ __align__(16) float g_mlp[B_ * MLPP];
__device__ __align__(16) float g_h[2][L_][8][16384];   // fragment order per 64-row group
__device__ __align__(16) float g_h7row[8][64][256];    // row-major h7 for fc
__device__ __align__(16) float g_c[L_][B_][H_];
__device__ __align__(16) float g_Wp[4194304];          // [l][p][bh16][kc8][512 f4]
__device__ __align__(16) float g_Wih0p[16][1024];
__device__ __align__(16) float g_W2tail[4096 * 32];
__device__ unsigned g_prog[128];

__device__ __forceinline__ float tf32f(float x) {
    uint32_t r; asm("cvt.rna.tf32.f32 %0, %1;" : "=r"(r) : "f"(x));
    return __uint_as_float(r);
}
#define U(x) __float_as_uint(x)
__device__ __forceinline__ void mma8(float c[4], uint32_t a0, uint32_t a1, uint32_t a2, uint32_t a3,
                                     uint32_t b0, uint32_t b1) {
    asm volatile("mma.sync.aligned.m16n8k8.row.col.f32.tf32.tf32.f32 "
                 "{%0,%1,%2,%3},{%4,%5,%6,%7},{%8,%9},{%0,%1,%2,%3};\n"
                 : "+f"(c[0]), "+f"(c[1]), "+f"(c[2]), "+f"(c[3])
                 : "r"(a0), "r"(a1), "r"(a2), "r"(a3), "r"(b0), "r"(b1));
}
__device__ __forceinline__ float sigf(float x) { return __fdividef(1.f, 1.f + __expf(-x)); }
__device__ __forceinline__ float tanhf_(float x) { return 2.f * sigf(2.f * x) - 1.f; }
__device__ __forceinline__ void cpa16(void* s, const void* g) {
    uint32_t sa = (uint32_t)__cvta_generic_to_shared(s);
    asm volatile("cp.async.cg.shared.global [%0], [%1], 16;" :: "r"(sa), "l"(g));
}
#define CP_COMMIT() asm volatile("cp.async.commit_group;\n")
#define CP_WAIT(n)  asm volatile("cp.async.wait_group %0;\n" :: "n"(n))

// float offset of (r,k) in fragment-ordered 64x256 tile
__device__ __forceinline__ int hfrag(int r, int k) {
    return ((((k >> 3) * 4 + (r >> 4)) * 32 + (r & 7) * 4 + (k & 3)) << 2)
           + ((r >> 3) & 1) + (((k >> 2) & 1) << 1);
}

__device__ __forceinline__ void mma_frag(const float4* Ac, const float4* Bc,
                                         float (&acc)[4][4], int wm, int wn, int lane) {
#pragma unroll
    for (int k8 = 0; k8 < 4; k8++) {
        float4 a  = Ac[(k8 * 4 + wm) * 32 + lane];
        float4 b0 = Bc[((k8 * 2 + wn) * 2 + 0) * 32 + lane];
        float4 b1 = Bc[((k8 * 2 + wn) * 2 + 1) * 32 + lane];
        mma8(acc[0], U(a.x), U(a.y), U(a.z), U(a.w), U(b0.x), U(b0.y));
        mma8(acc[1], U(a.x), U(a.y), U(a.z), U(a.w), U(b0.z), U(b0.w));
        mma8(acc[2], U(a.x), U(a.y), U(a.z), U(a.w), U(b1.x), U(b1.y));
        mma8(acc[3], U(a.x), U(a.y), U(a.z), U(a.w), U(b1.z), U(b1.w));
    }
}

// ---- prep: rollout weights -> fragment order ----
__global__ void __launch_bounds__(256) k_prep_w(const float* __restrict__ Whh0,
                                                const float* __restrict__ Wih,
                                                const float* __restrict__ Whh) {
    const int idx = blockIdx.x * 256 + threadIdx.x;
    const int comp = idx & 3, lane = (idx >> 2) & 31, p2 = (idx >> 7) & 1;
    const int wn = (idx >> 8) & 1, k8 = (idx >> 9) & 3, kc = (idx >> 11) & 7;
    const int bh = (idx >> 14) & 15, p = (idx >> 18) & 1, l = (idx >> 19) & 7;
    const int jn = wn * 4 + p2 * 2 + (comp >> 1);
    const int gc = jn * 8 + (lane >> 2);
    const int n = (gc >> 4) * 256 + bh * 16 + (gc & 15);
    const int k = kc * 32 + k8 * 8 + (comp & 1) * 4 + (lane & 3);
    float v = 0.f;
    if (l == 0) { if (p == 1) v = Whh0[n * 256 + k]; }
    else v = (p == 0) ? Wih[(size_t)(l - 1) * 262144 + n * 256 + k]
                      : Whh[(size_t)(l - 1) * 262144 + n * 256 + k];
    g_Wp[idx] = tf32f(v);
}

__global__ void __launch_bounds__(256) k_prep_small(const float* __restrict__ Wih0,
                                                    const float* __restrict__ W2) {
    const int i = blockIdx.x * 256 + threadIdx.x;
    if (i < 131072) {
        const int n = i >> 5, kk = i & 31;
        g_W2tail[i] = (kk < 24) ? tf32f(W2[(size_t)n * MLPH + 14976 + kk]) : 0.f;
    } else if (i < 131072 + 16384) {
        const int j = i - 131072;
        const int comp = j & 3, lane = (j >> 2) & 31, p2 = (j >> 7) & 1;
        const int wn = (j >> 8) & 1, k8 = (j >> 9) & 1, bh = j >> 10;
        const int jn = wn * 4 + p2 * 2 + (comp >> 1);
        const int gc = jn * 8 + (lane >> 2);
        const int n = (gc >> 4) * 256 + bh * 16 + (gc & 15);
        const int k = k8 * 8 + (comp & 1) * 4 + (lane & 3);
        g_Wih0p[bh][j & 1023] = (k < 14) ? tf32f(Wih0[n * 14 + k]) : 0.f;
    } else if (i < 131072 + 16384 + 4096) {
        const int j = i - 131072 - 16384;
        g_mlp[(size_t)(j >> 3) * MLPP + MLPH + (j & 7)] = 0.f;
    } else if (i < 131072 + 16384 + 4096 + 128) {
        g_prog[i - 131072 - 16384 - 4096] = 0u;
    }
}

// ---- GEMM1 (fp32 FFMA) ----
__global__ void __launch_bounds__(256) k_gemm1(const float* __restrict__ states,
                                               const float* __restrict__ acts,
                                               const float* __restrict__ W1,
                                               const float* __restrict__ b1) {
    const int bm = blockIdx.x & 15, bn = blockIdx.x >> 4, n0 = bn * 128;
    const int tid = threadIdx.x;
    __shared__ float enc_s[32][132];
    __shared__ float w_s[128][33];
    for (int i = tid; i < 32 * K1; i += 256) {
        const int r = i / K1, k = i % K1, b = bm * 32 + r;
        const int tt = k / 13, j = k % 13;
        enc_s[r][k] = (j < 9) ? states[(b * T_ + tt) * 12 + 3 + j]
                              : acts[(b * T_ + tt) * 4 + (j - 9)];
    }
    float acc[4][4];
#pragma unroll
    for (int a = 0; a < 4; a++)
#pragma unroll
        for (int b = 0; b < 4; b++) acc[a][b] = 0.f;
    const int tr = tid >> 5, tc = tid & 31;
    for (int k0 = 0; k0 < K1; k0 += 32) {
        const int kn = min(32, K1 - k0);
        __syncthreads();
        for (int i = tid; i < 4096; i += 256) {
            const int c = i >> 5, kk = i & 31, n = n0 + c;
            w_s[c][kk] = (kk < kn && n < MLPH) ? W1[n * K1 + k0 + kk] : 0.f;
        }
        __syncthreads();
        for (int kk = 0; kk < kn; kk++) {
            float a[4], w[4];
#pragma unroll
            for (int x = 0; x < 4; x++) a[x] = enc_s[tr + 8 * x][k0 + kk];
#pragma unroll
            for (int y = 0; y < 4; y++) w[y] = w_s[tc + 32 * y][kk];
#pragma unroll
            for (int x = 0; x < 4; x++)
#pragma unroll
                for (int y = 0; y < 4; y++) acc[x][y] += a[x] * w[y];
        }
    }
#pragma unroll
    for (int x = 0; x < 4; x++)
#pragma unroll
        for (int y = 0; y < 4; y++) {
            const int b = bm * 32 + tr + 8 * x, n = n0 + tc + 32 * y;
            if (n < MLPH) g_mlp[(size_t)b * MLPP + n] = tf32f(fmaxf(acc[x][y] + b1[n], 0.f));
        }
}

// ---- GEMM2: 3-stage pipeline, single sync/chunk ----
__global__ void __launch_bounds__(256) k_gemm2(const float* __restrict__ W2,
                                               const float* __restrict__ b2) {
    const int bm = blockIdx.x & 7, bn = blockIdx.x >> 3;
    const int tid = threadIdx.x;
    const int warp = tid >> 5, lane = tid & 31;
    const int wm = warp >> 1, wn = warp & 1;
    const int g = lane >> 2, tq = lane & 3;
    extern __shared__ __align__(16) float sm[];
    float (*As)[64][36] = (float(*)[64][36])sm;
    float (*Bs)[64][36] = (float(*)[64][36])(sm + 3 * 64 * 36);

    float acc[4][4];
#pragma unroll
    for (int j = 0; j < 4; j++)
#pragma unroll
        for (int d = 0; d < 4; d++) acc[j][d] = 0.f;

    auto stage = [&](int buf, int c) {
        const int k0 = c * 32;
#pragma unroll
        for (int q = 0; q < 2; q++) {
            const int s = tid + q * 256;
            const int r = s >> 3, kq = (s & 7) << 2;
            cpa16(&As[buf][r][kq], &g_mlp[(size_t)(bm * 64 + r) * MLPP + k0 + kq]);
            const float* bsrc = (c < 468) ? (W2 + (size_t)(bn * 64 + r) * MLPH + k0 + kq)
                                          : (&g_W2tail[(bn * 64 + r) * 32 + kq]);
            cpa16(&Bs[buf][r][kq], bsrc);
        }
        CP_COMMIT();
    };
    stage(0, 0); stage(1, 1);
    for (int c = 0; c < NCH2; c++) {
        if (c < NCH2 - 1) CP_WAIT(1); else CP_WAIT(0);
        __syncthreads();
        if (c + 2 < NCH2) stage((c + 2) % 3, c + 2);
        const int buf = c % 3;
#pragma unroll
        for (int k8 = 0; k8 < 4; k8++) {
            const int kc = k8 * 8 + tq, ar = wm * 16 + g;
            uint32_t a0 = U(As[buf][ar][kc]), a1 = U(As[buf][ar + 8][kc]);
            uint32_t a2 = U(As[buf][ar][kc + 4]), a3 = U(As[buf][ar + 8][kc + 4]);
#pragma unroll
            for (int j = 0; j < 4; j++) {
                const int bc = wn * 32 + j * 8 + g;
                mma8(acc[j], a0, a1, a2, a3, U(Bs[buf][bc][kc]), U(Bs[buf][bc][kc + 4]));
            }
        }
    }
#pragma unroll
    for (int j = 0; j < 4; j++)
#pragma unroll
        for (int d = 0; d < 4; d++) {
            const int r = wm * 16 + g + ((d & 2) ? 8 : 0);
            const int c = wn * 32 + j * 8 + tq * 2 + (d & 1);
            const int n = bn * 64 + c;
            const float v = acc[j][d] + b2[n];
            const int l = n >> 9, rem = n & 511;
            if (rem < H_) g_h[1][l][bm][hfrag(r, rem)] = tf32f(v);
            else          g_c[l][bm * 64 + r][rem - H_] = v;
        }
}

// ---- rollout ----
__global__ void __launch_bounds__(256) k_rollout(
    const float* __restrict__ states, const float* __restrict__ acts,
    const float* __restrict__ dts,
    const float* __restrict__ bih0, const float* __restrict__ bhh0,
    const float* __restrict__ bih, const float* __restrict__ bhh,
    const float* __restrict__ Wfc, const float* __restrict__ bfc,
    float* __restrict__ out)
{
    const int rg = blockIdx.x >> 4, bh = blockIdx.x & 15;
    const int tid = threadIdx.x;
    const int warp = tid >> 5, lane = tid & 31;
    const int wm = warp >> 1, wn = warp & 1;
    const int g = lane >> 2, tq = lane & 3;
    const int row0 = rg * 64, hc0 = bh * 16;

    extern __shared__ __align__(16) float sm[];
    float4* A4 = (float4*)sm;                 // 3*512
    float4* B4 = (float4*)(sm + 6144);        // 3*512
    float4* AX = (float4*)(sm + 12288);       // 256
    float4* BX = (float4*)(sm + 13312);       // 256
    float (*Gs)[68]   = (float(*)[68])(sm + 14336);
    float (*xs)[16]   = (float(*)[16])(sm + 18688);
    float (*bias)[64] = (float(*)[64])(sm + 19712);

#pragma unroll
    for (int q = 0; q < 1; q++) cpa16(&BX[tid], &((const float4*)g_Wih0p[bh])[tid]);
    CP_COMMIT();

    for (int i = tid; i < 512; i += 256) {
        const int l = i >> 6, gc = i & 63;
        const int n = (gc >> 4) * 256 + hc0 + (gc & 15);
        bias[l][gc] = (l == 0) ? __ldg(&bih0[n]) + __ldg(&bhh0[n])
                               : __ldg(&bih[(l - 1) * 1024 + n]) + __ldg(&bhh[(l - 1) * 1024 + n]);
    }
    float c_reg[8][4];
#pragma unroll
    for (int l = 0; l < 8; l++)
#pragma unroll
        for (int e = 0; e < 4; e++) {
            const int lin = tid + 256 * e;
            c_reg[l][e] = __ldcg(&g_c[l][row0 + (lin >> 4)][hc0 + (lin & 15)]);
        }
    for (int i = tid; i < 576; i += 256) {
        const int r = i / 9, j = i % 9;
        xs[r][1 + j] = states[((row0 + r) * T_ + HIST) * 12 + 3 + j];
    }
    if (tid < 128) xs[tid >> 1][14 + (tid & 1)] = 0.f;
    CP_WAIT(0);
    __syncthreads();

    auto stageAB = [&](int s, const float4* Ag, const float4* Bg) {
        cpa16(&A4[s * 512 + tid], Ag + tid);
        cpa16(&A4[s * 512 + tid + 256], Ag + tid + 256);
        cpa16(&B4[s * 512 + tid], Bg + tid);
        cpa16(&B4[s * 512 + tid + 256], Bg + tid + 256);
        CP_COMMIT();
    };

    for (int t = 0; t < NSTEP; t++) {
        const int cur = t & 1, old = cur ^ 1;
        if (tid < 64) xs[tid][0] = dts[(row0 + tid) * T_ + HIST + 1 + t];
        { const int r = tid >> 2, j = tid & 3;
          xs[r][10 + j] = acts[((row0 + r) * T_ + HIST + t) * 4 + j]; }
        __syncthreads();

        for (int l = 0; l < 8; l++) {
            float acc[4][4];
#pragma unroll
            for (int j = 0; j < 4; j++)
#pragma unroll
                for (int d = 0; d < 4; d++) acc[j][d] = 0.f;

            // pass 1 (h_old @ Whh) — no dependency wait
            {
                const float4* Ag = (const float4*)&g_h[old][l][rg][0];
                const float4* Bg = (const float4*)(g_Wp + (size_t)((l * 2 + 1) * 16 + bh) * 16384);
                stageAB(0, Ag, Bg); stageAB(1, Ag + 512, Bg + 512);
                if (l == 0) {  // x-tile mma first
                    const int k8 = tid >> 7, wmx = (tid >> 5) & 3, ln = tid & 31;
                    const int gg = ln >> 2, tt = ln & 3;
                    float4 v;
                    v.x = tf32f(xs[wmx * 16 + gg][k8 * 8 + tt]);
                    v.y = tf32f(xs[wmx * 16 + gg + 8][k8 * 8 + tt]);
                    v.z = tf32f(xs[wmx * 16 + gg][k8 * 8 + tt + 4]);
                    v.w = tf32f(xs[wmx * 16 + gg + 8][k8 * 8 + tt + 4]);
                    AX[tid] = v;
                    __syncthreads();
#pragma unroll
                    for (int k8i = 0; k8i < 2; k8i++) {
                        float4 a  = AX[(k8i * 4 + wm) * 32 + lane];
                        float4 b0 = BX[((k8i * 2 + wn) * 2 + 0) * 32 + lane];
                        float4 b1 = BX[((k8i * 2 + wn) * 2 + 1) * 32 + lane];
                        mma8(acc[0], U(a.x), U(a.y), U(a.z), U(a.w), U(b0.x), U(b0.y));
                        mma8(acc[1], U(a.x), U(a.y), U(a.z), U(a.w), U(b0.z), U(b0.w));
                        mma8(acc[2], U(a.x), U(a.y), U(a.z), U(a.w), U(b1.x), U(b1.y));
                        mma8(acc[3], U(a.x), U(a.y), U(a.z), U(a.w), U(b1.z), U(b1.w));
                    }
                }
                for (int kc = 0; kc < 8; kc++) {
                    if (kc < 7) CP_WAIT(1); else CP_WAIT(0);
                    __syncthreads();
                    if (kc + 2 < 8) stageAB((kc + 2) % 3, Ag + (kc + 2) * 512, Bg + (kc + 2) * 512);
                    mma_frag(A4 + (kc % 3) * 512, B4 + (kc % 3) * 512, acc, wm, wn, lane);
                }
            }
            // pass 0 (h_cur[l-1] @ Wih) — needs dependency
            if (l > 0) {
                const unsigned tgt = (unsigned)(t * 8 + l);
                if (tid < 16) {
                    while (((volatile unsigned*)g_prog)[rg * 16 + tid] < tgt) __nanosleep(32);
                    __threadfence();
                }
                __syncthreads();
                const float4* Ag = (const float4*)&g_h[cur][l - 1][rg][0];
                const float4* Bg = (const float4*)(g_Wp + (size_t)((l * 2 + 0) * 16 + bh) * 16384);
                stageAB(0, Ag, Bg); stageAB(1, Ag + 512, Bg + 512);
                for (int kc = 0; kc < 8; kc++) {
                    if (kc < 7) CP_WAIT(1); else CP_WAIT(0);
                    __syncthreads();
                    if (kc + 2 < 8) stageAB((kc + 2) % 3, Ag + (kc + 2) * 512, Bg + (kc + 2) * 512);
                    mma_frag(A4 + (kc % 3) * 512, B4 + (kc % 3) * 512, acc, wm, wn, lane);
                }
            }
            // gates -> Gs
#pragma unroll
            for (int j = 0; j < 4; j++)
#pragma unroll
                for (int d = 0; d < 4; d++) {
                    const int rr = wm * 16 + g + ((d & 2) ? 8 : 0);
                    const int cc = (wn * 4 + j) * 8 + tq * 2 + (d & 1);
                    Gs[rr][cc] = acc[j][d];
                }
            __syncthreads();
            // elementwise
            float* hdst = &g_h[cur][l][rg][0];
#pragma unroll
            for (int e = 0; e < 4; e++) {
                const int lin = tid + 256 * e;
                const int r = lin >> 4, hc = lin & 15;
                float iG = Gs[r][hc]      + bias[l][hc];
                float fG = Gs[r][16 + hc] + bias[l][16 + hc];
                float gG = Gs[r][32 + hc] + bias[l][32 + hc];
                float oG = Gs[r][48 + hc] + bias[l][48 + hc];
                const float cn = sigf(fG) * c_reg[l][e] + sigf(iG) * tanhf_(gG);
                c_reg[l][e] = cn;
                const float hv = tf32f(sigf(oG) * tanhf_(cn));
                hdst[hfrag(r, hc0 + hc)] = hv;
                if (l == 7) g_h7row[rg][r][hc0 + hc] = hv;
            }
            __threadfence();
            __syncthreads();
            if (tid == 0)
                *(volatile unsigned*)&g_prog[rg * 16 + bh] = (unsigned)(t * 8 + l + 1);
        }

        // wait full step done in this rowgroup
        if (tid < 16) {
            const unsigned tgt = (unsigned)(t * 8 + 8);
            while (((volatile unsigned*)g_prog)[rg * 16 + tid] < tgt) __nanosleep(32);
            __threadfence();
        }
        __syncthreads();

        // fc: 64 rows x 9 outs
        const int r1 = tid >> 3, o1 = tid & 7;
        float pa = __ldg(&bfc[o1]), pb = __ldg(&bfc[o1]);
        float pc = (tid < 64) ? __ldg(&bfc[8]) : 0.f;
        for (int qq = 0; qq < 4; qq++) {
            __syncthreads();
#pragma unroll
            for (int q = 0; q < 4; q++) {
                const int i = tid + 256 * q;
                const int r = i >> 4, kq = (i & 15) << 2;
                float4 v = __ldcg((const float4*)&g_h7row[rg][r][qq * 64 + kq]);
                Gs[r][kq] = v.x; Gs[r][kq + 1] = v.y; Gs[r][kq + 2] = v.z; Gs[r][kq + 3] = v.w;
            }
            __syncthreads();
#pragma unroll 4
            for (int k = 0; k < 64; k++) {
                const float w = __ldg(&Wfc[o1 * 256 + qq * 64 + k]);
                pa += Gs[r1][k] * w;
                pb += Gs[r1 + 32][k] * w;
                if (tid < 64) pc += Gs[tid][k] * __ldg(&Wfc[8 * 256 + qq * 64 + k]);
            }
        }
        __syncthreads();
        xs[r1][1 + o1] = pa;
        xs[r1 + 32][1 + o1] = pb;
        if (tid < 64) xs[tid][9] = pc;
        if (bh == 0) {
            out[(size_t)(row0 + r1) * (NSTEP * 9) + t * 9 + o1] = pa;
            out[(size_t)(row0 + r1 + 32) * (NSTEP * 9) + t * 9 + o1] = pb;
            if (tid < 64) out[(size_t)(row0 + tid) * (NSTEP * 9) + t * 9 + 8] = pc;
        }
        __syncthreads();
    }
}

extern "C" void kernel_launch(void* const* d_in, const int* in_sizes, int n_in,
                              void* d_out, int out_size) {
    const float* states = (const float*)d_in[0];
    const float* acts   = (const float*)d_in[1];
    const float* dts    = (const float*)d_in[2];
    const float* W1     = (const float*)d_in[3];
    const float* b1     = (const float*)d_in[4];
    const float* W2     = (const float*)d_in[5];
    const float* b2     = (const float*)d_in[6];
    const float* Wih0   = (const float*)d_in[7];
    const float* Whh0   = (const float*)d_in[8];
    const float* bih0   = (const float*)d_in[9];
    const float* bhh0   = (const float*)d_in[10];
    const float* Wih    = (const float*)d_in[11];
    const float* Whh    = (const float*)d_in[12];
    const float* bih    = (const float*)d_in[13];
    const float* bhh    = (const float*)d_in[14];
    const float* Wfc    = (const float*)d_in[15];
    const float* bfc    = (const float*)d_in[16];
    float* out = (float*)d_out;

    const int sm2 = 3 * 64 * 36 * 2 * 4;
    const int smr = 20224 * 4;
    cudaFuncSetAttribute(k_gemm2, cudaFuncAttributeMaxDynamicSharedMemorySize, sm2);
    cudaFuncSetAttribute(k_rollout, cudaFuncAttributeMaxDynamicSharedMemorySize, smr);

    k_prep_w<<<16384, 256>>>(Whh0, Wih, Whh);
    k_prep_small<<<593, 256>>>(Wih0, W2);
    k_gemm1<<<16 * 118, 256>>>(states, acts, W1, b1);
    k_gemm2<<<512, 256, sm2>>>(W2, b2);
    k_rollout<<<128, 256, smr>>>(states, acts, dts, bih0, bhh0,
                                 bih, bhh, Wfc, bfc, out);
}